// round 17
// baseline (speedup 1.0000x reference)
#include <cuda_runtime.h>
#include <cstdint>

#define NB 8
#define S_LEN 4096
#define D 1024
#define D4 (D / 4)        // 256 float4 per row
#define G 512             // persistent grid: 4 blocks/SM x 148 = 592 >= 512
#define T 256
#define SLICES 64         // V row-slices per batch (G = NB * SLICES)
#define ROWS_PER_SLICE (S_LEN / SLICES)  // 64
#define JPB 2             // j columns per block (512 * 2 = 1024)

// Scratch (allocation-free rule: __device__ globals). 16B-aligned for TMA bulk.
__device__ __align__(16) float g_partial[NB * SLICES * D];  // 2 MB
__device__ __align__(16) float g_vsum[NB * D];
__device__ __align__(16) float g_tmp[NB * D];
__device__ unsigned int g_bar[4];  // zero-initialized; monotonic tickets

// xs(32K) + wsv(8K) + wso(8K) + sout(256B) = 49.4 KB -> 4 blocks/SM
#define FUSED_SMEM ((2048 + 512 + 512) * 16 + 64 * 4)

__device__ __forceinline__ void bulk_g2s(uint32_t dst, const void* src,
                                         uint32_t bytes, uint32_t mbar) {
    asm volatile(
        "cp.async.bulk.shared::cta.global.mbarrier::complete_tx::bytes "
        "[%0], [%1], %2, [%3];"
        :: "r"(dst), "l"(src), "r"(bytes), "r"(mbar) : "memory");
}

// Grid barrier: monotonic counter, replay-safe (each replay adds exactly G).
__device__ __forceinline__ void grid_barrier(int i) {
    __threadfence();
    __syncthreads();
    if (threadIdx.x == 0) {
        unsigned int ticket = atomicAdd(&g_bar[i], 1u);
        unsigned int target = (ticket / G + 1u) * G;
        while (atomicAdd(&g_bar[i], 0u) < target) {}
        __threadfence();
    }
    __syncthreads();
}

__global__ void __launch_bounds__(T) fused(const float4* __restrict__ V,
                                           const float4* __restrict__ Wv,
                                           const float*  __restrict__ bv,
                                           const float4* __restrict__ Wo,
                                           const float*  __restrict__ bo,
                                           float* __restrict__ out) {
    extern __shared__ __align__(16) float4 dyn[];
    float4* xs   = dyn;           // 2048 float4: x tile (8 x 256)
    float4* wsv  = dyn + 2048;    // 512 float4: Wv rows j0, j0+1
    float4* wso  = dyn + 2560;    // 512 float4: Wo rows j0, j0+1
    float*  sout = reinterpret_cast<float*>(dyn + 3072);  // [4 kq][2 j][8 n]
    __shared__ __align__(8) unsigned long long mbar;

    const int t = threadIdx.x;
    const int lane = t & 31;
    const int wid = t >> 5;      // 0..7
    const int b = blockIdx.x;

    const uint32_t mbar_a = (uint32_t)__cvta_generic_to_shared(&mbar);

    // ---- t=0: TMA-prefetch this block's W tiles (16 KB); hides under phase 1
    if (t == 0) {
        asm volatile("mbarrier.init.shared.b64 [%0], %1;"
                     :: "r"(mbar_a), "r"(1) : "memory");
        asm volatile("mbarrier.arrive.expect_tx.shared.b64 _, [%0], %1;"
                     :: "r"(mbar_a), "r"(2 * JPB * 4096) : "memory");
        bulk_g2s((uint32_t)__cvta_generic_to_shared(wsv),
                 Wv + (size_t)b * JPB * D4, JPB * 4096, mbar_a);
        bulk_g2s((uint32_t)__cvta_generic_to_shared(wso),
                 Wo + (size_t)b * JPB * D4, JPB * 4096, mbar_a);
    }

    // ---- Phase 1: V column partial sums — proven 512-block geometry ----
    // (4 blocks/SM x 8 warps x MLP4 ~= 112+ outstanding lines/SM)
    {
        const int n = b >> 6;         // 0..7
        const int slice = b & 63;     // 0..63
        const float4* base =
            V + ((size_t)n * S_LEN + (size_t)slice * ROWS_PER_SLICE) * D4 + t;
        float4 a0 = make_float4(0.f, 0.f, 0.f, 0.f);
        float4 a1 = a0, a2 = a0, a3 = a0;
#pragma unroll 4
        for (int s = 0; s < ROWS_PER_SLICE; s += 4) {
            float4 v0 = base[(size_t)(s + 0) * D4];
            float4 v1 = base[(size_t)(s + 1) * D4];
            float4 v2 = base[(size_t)(s + 2) * D4];
            float4 v3 = base[(size_t)(s + 3) * D4];
            a0.x += v0.x; a0.y += v0.y; a0.z += v0.z; a0.w += v0.w;
            a1.x += v1.x; a1.y += v1.y; a1.z += v1.z; a1.w += v1.w;
            a2.x += v2.x; a2.y += v2.y; a2.z += v2.z; a2.w += v2.w;
            a3.x += v3.x; a3.y += v3.y; a3.z += v3.z; a3.w += v3.w;
        }
        float4 acc;
        acc.x = (a0.x + a1.x) + (a2.x + a3.x);
        acc.y = (a0.y + a1.y) + (a2.y + a3.y);
        acc.z = (a0.z + a1.z) + (a2.z + a3.z);
        acc.w = (a0.w + a1.w) + (a2.w + a3.w);
        // layout: [(n*64 + slice) * 256 + col]
        reinterpret_cast<float4*>(g_partial)[(size_t)b * D4 + t] = acc;
    }

    grid_barrier(0);

    // ---- Phase 2: fold 64 partials per element ----
    // Warps 0..3: warp w owns element e = b*4 + w (of 2048 float4 elements).
    // Lane l sums slices l and l+32, then 32-lane shfl reduce.
    if (wid < 4) {
        const int e = b * 4 + wid;
        const int n = e >> 8;
        const int col = e & 255;
        const float4* p = reinterpret_cast<const float4*>(g_partial) +
                          ((size_t)n * SLICES) * D4 + col;
        float4 v0 = p[(size_t)lane * D4];
        float4 v1 = p[(size_t)(lane + 32) * D4];
        float4 v;
        v.x = v0.x + v1.x; v.y = v0.y + v1.y;
        v.z = v0.z + v1.z; v.w = v0.w + v1.w;
#pragma unroll
        for (int ofs = 16; ofs > 0; ofs >>= 1) {
            v.x += __shfl_xor_sync(0xFFFFFFFFu, v.x, ofs);
            v.y += __shfl_xor_sync(0xFFFFFFFFu, v.y, ofs);
            v.z += __shfl_xor_sync(0xFFFFFFFFu, v.z, ofs);
            v.w += __shfl_xor_sync(0xFFFFFFFFu, v.w, ofs);
        }
        if (lane == 0)
            reinterpret_cast<float4*>(g_vsum)[(size_t)n * D4 + col] = v;
    }

    grid_barrier(1);

    // W tiles long since arrived (overlapped with phase 1).
    {
        uint32_t done = 0;
        while (!done) {
            asm volatile(
                "{\n\t.reg .pred p;\n\t"
                "mbarrier.try_wait.parity.acquire.cta.shared::cta.b64 p, [%1], %2;\n\t"
                "selp.b32 %0, 1, 0, p;\n\t}"
                : "=r"(done) : "r"(mbar_a), "r"(0) : "memory");
        }
    }
    __syncthreads();

    // ---- Phase 3 + 4: two gemvs against smem-resident W tiles ----
    // 8 warps = 2 j x 4 k-quarters. Warp: jl = wid&1, kq = wid>>1.
#pragma unroll
    for (int stage = 0; stage < 2; ++stage) {
        const float4* xin = reinterpret_cast<const float4*>(
            stage == 0 ? g_vsum : g_tmp);
        const float4* ws = (stage == 0) ? wsv : wso;
        const float*  bias = (stage == 0) ? bv : bo;
        const float   bscale = (stage == 0) ? (float)S_LEN : 1.0f;
        float* o = (stage == 0) ? g_tmp : out;

        // Stage x (32 KB, L2-hot): 8 float4/thread, coalesced.
#pragma unroll
        for (int i = t; i < NB * D4; i += T) xs[i] = xin[i];
        __syncthreads();

        const int jl = wid & 1;
        const int kq = wid >> 1;   // 0..3 -> chunks kq*2, kq*2+1

        float acc[NB];
#pragma unroll
        for (int n = 0; n < NB; ++n) acc[n] = 0.f;
#pragma unroll
        for (int ii = 0; ii < 2; ++ii) {
            const int c = kq * 2 + ii;
            float4 w = ws[jl * D4 + c * 32 + lane];
#pragma unroll
            for (int n = 0; n < NB; ++n) {
                float4 x = xs[n * D4 + c * 32 + lane];
                acc[n] += w.x * x.x + w.y * x.y + w.z * x.z + w.w * x.w;
            }
        }
#pragma unroll
        for (int n = 0; n < NB; ++n) {
#pragma unroll
            for (int ofs = 16; ofs > 0; ofs >>= 1)
                acc[n] += __shfl_xor_sync(0xFFFFFFFFu, acc[n], ofs);
        }
        if (lane == 0) {
#pragma unroll
            for (int n = 0; n < NB; ++n)
                sout[kq * 16 + jl * NB + n] = acc[n];
        }
        __syncthreads();
        if (t < JPB * NB) {   // 16 outputs: fold the 4 k-quarters
            const int jl2 = t >> 3;
            const int n   = t & 7;
            const int j   = b * JPB + jl2;
            float s = sout[jl2 * NB + n] + sout[16 + jl2 * NB + n] +
                      sout[32 + jl2 * NB + n] + sout[48 + jl2 * NB + n];
            o[n * D + j] = s + bscale * bias[j];
        }

        if (stage == 0) grid_barrier(2);  // g_tmp fully written before phase 4
        else __syncthreads();
    }
}

// ---------------------------------------------------------------------------
extern "C" void kernel_launch(void* const* d_in, const int* in_sizes, int n_in,
                              void* d_out, int out_size) {
    (void)in_sizes; (void)n_in; (void)out_size;
    // metadata order: Q(0) K(1) V(2) Wq(3) bq(4) Wk(5) bk(6) Wv(7) bv(8) Wo(9) bo(10)
    // softmax over a size-1 axis == 1.0 -> Q, K, Wq, bq, Wk, bk are dead inputs.
    const float4* V  = (const float4*)d_in[2];
    const float4* Wv = (const float4*)d_in[7];
    const float*  bv = (const float*)d_in[8];
    const float4* Wo = (const float4*)d_in[9];
    const float*  bo = (const float*)d_in[10];
    float* out = (float*)d_out;

    // Not a stream op; safe under graph capture. Idempotent.
    cudaFuncSetAttribute(fused, cudaFuncAttributeMaxDynamicSharedMemorySize,
                         FUSED_SMEM);

    fused<<<G, T, FUSED_SMEM>>>(V, Wv, bv, Wo, bo, out);
}